// round 15
// baseline (speedup 1.0000x reference)
#include <cuda_runtime.h>
#include <cuda_bf16.h>
#include <math.h>
#include <stdint.h>

#define HID   1024
#define VOCAB 32000
#define BATCH 64
#define ROWS_FINAL (BATCH * 32)      // 2048
#define BKP 40                        // tree GEMM smem row stride (32 + 8 pad)
#define IKP 80                        // int8 GEMM smem row stride BYTES (64 + 16 pad)

// ---------------- static device scratch (no allocations allowed) ----------------
__device__ float g_hA[ROWS_FINAL * HID];                 // fp32 h ping
__device__ float g_hB[ROWS_FINAL * HID];                 // fp32 h pong
__device__ __nv_bfloat16 g_hAb[ROWS_FINAL * HID];        // bf16 h ping
__device__ __nv_bfloat16 g_hBb[ROWS_FINAL * HID];        // bf16 h pong
__device__ __nv_bfloat16 g_encb[BATCH * HID];            // bf16 encoding
__device__ __nv_bfloat16 g_wlb[3 * HID * HID];           // bf16 Whh_l
__device__ __nv_bfloat16 g_wrb[3 * HID * HID];           // bf16 Whh_r
__device__ float g_gl[1024 * 3 * HID];                   // split-K partials
__device__ float g_gr[1024 * 3 * HID];
__device__ int8_t g_wq[(size_t)VOCAB * HID];             // int8 Wout (scale 1/4064)
__device__ int8_t g_hq[ROWS_FINAL * HID];                // int8 h (per-row scale)
__device__ float  g_hscale[ROWS_FINAL];
__device__ __nv_bfloat16 g_logitsb[(size_t)ROWS_FINAL * VOCAB]; // bf16 logits

// ---------------- one-time conversions -------------------------------------------
__global__ void convert_init_k(const float* __restrict__ wl, const float* __restrict__ wr,
                               const float* __restrict__ enc,
                               __nv_bfloat16* __restrict__ wlb, __nv_bfloat16* __restrict__ wrb,
                               __nv_bfloat16* __restrict__ encb)
{
    const long nW = 3L * HID * HID / 2;
    const long ne = BATCH * HID / 2;
    const long tot = 2 * nW + ne;
    for (long i = (long)blockIdx.x * blockDim.x + threadIdx.x; i < tot;
         i += (long)gridDim.x * blockDim.x) {
        const float2* src; __nv_bfloat162* dst; long off;
        if (i < nW)          { src = (const float2*)wl;  dst = (__nv_bfloat162*)wlb;  off = i; }
        else if (i < 2 * nW) { src = (const float2*)wr;  dst = (__nv_bfloat162*)wrb;  off = i - nW; }
        else                 { src = (const float2*)enc; dst = (__nv_bfloat162*)encb; off = i - 2 * nW; }
        float2 v = src[off];
        dst[off] = __floats2bfloat162_rn(v.x, v.y);
    }
}

__global__ void quant_w_k(const float* __restrict__ wo, int8_t* __restrict__ wq)
{
    const long n4 = (long)VOCAB * HID / 4;
    for (long i = (long)blockIdx.x * blockDim.x + threadIdx.x; i < n4;
         i += (long)gridDim.x * blockDim.x) {
        float4 v = ((const float4*)wo)[i];
        char4 q;
        q.x = (char)max(-127.f, min(127.f, rintf(v.x * 4064.f)));
        q.y = (char)max(-127.f, min(127.f, rintf(v.y * 4064.f)));
        q.z = (char)max(-127.f, min(127.f, rintf(v.z * 4064.f)));
        q.w = (char)max(-127.f, min(127.f, rintf(v.w * 4064.f)));
        ((char4*)wq)[i] = q;
    }
}

__global__ __launch_bounds__(256) void quant_h_k(const float* __restrict__ h,
                                                 int8_t* __restrict__ hq,
                                                 float* __restrict__ hscale)
{
    __shared__ float smax[8];
    const int row = blockIdx.x;
    const int t = threadIdx.x;
    const float4 v = ((const float4*)(h + (size_t)row * HID))[t];
    float m = fmaxf(fmaxf(fabsf(v.x), fabsf(v.y)), fmaxf(fabsf(v.z), fabsf(v.w)));
#pragma unroll
    for (int o = 16; o; o >>= 1) m = fmaxf(m, __shfl_xor_sync(0xffffffffu, m, o));
    if ((t & 31) == 0) smax[t >> 5] = m;
    __syncthreads();
    float rm = fmaxf(fmaxf(fmaxf(smax[0], smax[1]), fmaxf(smax[2], smax[3])),
                     fmaxf(fmaxf(smax[4], smax[5]), fmaxf(smax[6], smax[7])));
    rm = fmaxf(rm, 1e-8f);
    const float inv = 127.f / rm;
    char4 q;
    q.x = (char)rintf(v.x * inv);
    q.y = (char)rintf(v.y * inv);
    q.z = (char)rintf(v.z * inv);
    q.w = (char)rintf(v.w * inv);
    ((char4*)(hq + (size_t)row * HID))[t] = q;
    if (t == 0) hscale[row] = rm / 127.f;
}

// ---------------- tree-level GEMM (mma.sync; split-K fused L/R) ------------------
__global__ __launch_bounds__(256) void gemm_k(
    const __nv_bfloat16* __restrict__ A,
    const void* __restrict__ Bl, const void* __restrict__ Br,
    float* __restrict__ Cl, float* __restrict__ Cr,
    int M, int N, int K, int ksplit)
{
    __shared__ __nv_bfloat16 As[2][128][BKP];
    __shared__ __nv_bfloat16 Bs[2][128][BKP];

    const int tid  = threadIdx.x;
    const int lane = tid & 31;
    const int warp = tid >> 5;
    const int wm   = warp & 3;
    const int wn   = warp >> 2;
    const int blockM = blockIdx.x * 128;
    const int blockN = blockIdx.y * 128;

    int w = blockIdx.z & 1, part = blockIdx.z >> 1;
    const void* Bv = w ? Br : Bl;
    float* C = (w ? Cr : Cl) + (size_t)part * M * N;
    const int Kc  = K / ksplit;
    const int k0b = part * Kc;

    float acc[2][8][4];
#pragma unroll
    for (int mi = 0; mi < 2; ++mi)
#pragma unroll
        for (int nj = 0; nj < 8; ++nj)
#pragma unroll
            for (int q = 0; q < 4; ++q) acc[mi][nj][q] = 0.f;

    uint4 aR[2], bRh[2];

    {
        const int k0 = k0b;
#pragma unroll
        for (int j = 0; j < 2; ++j) {
            int idx = tid + (j << 8);
            int r = idx >> 2, c = (idx & 3) << 3;
            int grow = blockM + r;
            aR[j] = (grow < M) ? *(const uint4*)(A + (size_t)grow * K + k0 + c)
                               : make_uint4(0, 0, 0, 0);
            bRh[j] = *(const uint4*)((const __nv_bfloat16*)Bv + (size_t)(blockN + r) * K + k0 + c);
        }
#pragma unroll
        for (int j = 0; j < 2; ++j) {
            int idx = tid + (j << 8);
            int r = idx >> 2, c = (idx & 3) << 3;
            *(uint4*)&As[0][r][c] = aR[j];
            *(uint4*)&Bs[0][r][c] = bRh[j];
        }
    }
    __syncthreads();

    const int kTiles = Kc >> 5;
    for (int kt = 0; kt < kTiles; ++kt) {
        const int cur = kt & 1;
        const bool have_next = (kt + 1 < kTiles);
        if (have_next) {
            const int k0 = k0b + ((kt + 1) << 5);
#pragma unroll
            for (int j = 0; j < 2; ++j) {
                int idx = tid + (j << 8);
                int r = idx >> 2, c = (idx & 3) << 3;
                int grow = blockM + r;
                aR[j] = (grow < M) ? *(const uint4*)(A + (size_t)grow * K + k0 + c)
                                   : make_uint4(0, 0, 0, 0);
                bRh[j] = *(const uint4*)((const __nv_bfloat16*)Bv + (size_t)(blockN + r) * K + k0 + c);
            }
        }

#pragma unroll
        for (int kk = 0; kk < 2; ++kk) {
            uint32_t af[2][4];
#pragma unroll
            for (int mi = 0; mi < 2; ++mi) {
                int row = wm * 32 + mi * 16 + (lane & 15);
                int col = kk * 16 + (lane >> 4) * 8;
                uint32_t addr = (uint32_t)__cvta_generic_to_shared(&As[cur][row][col]);
                asm volatile("ldmatrix.sync.aligned.m8n8.x4.shared.b16 {%0,%1,%2,%3}, [%4];\n"
                             : "=r"(af[mi][0]), "=r"(af[mi][1]), "=r"(af[mi][2]), "=r"(af[mi][3])
                             : "r"(addr));
            }
            uint32_t bfr[8][2];
#pragma unroll
            for (int njp = 0; njp < 4; ++njp) {
                int nrow = wn * 64 + njp * 16 + ((lane >> 4) << 3) + (lane & 7);
                int col  = kk * 16 + ((lane >> 3) & 1) * 8;
                uint32_t addr = (uint32_t)__cvta_generic_to_shared(&Bs[cur][nrow][col]);
                asm volatile("ldmatrix.sync.aligned.m8n8.x4.shared.b16 {%0,%1,%2,%3}, [%4];\n"
                             : "=r"(bfr[2 * njp][0]), "=r"(bfr[2 * njp][1]),
                               "=r"(bfr[2 * njp + 1][0]), "=r"(bfr[2 * njp + 1][1])
                             : "r"(addr));
            }
#pragma unroll
            for (int mi = 0; mi < 2; ++mi)
#pragma unroll
                for (int nj = 0; nj < 8; ++nj)
                    asm volatile(
                        "mma.sync.aligned.m16n8k16.row.col.f32.bf16.bf16.f32 "
                        "{%0,%1,%2,%3}, {%4,%5,%6,%7}, {%8,%9}, {%0,%1,%2,%3};\n"
                        : "+f"(acc[mi][nj][0]), "+f"(acc[mi][nj][1]),
                          "+f"(acc[mi][nj][2]), "+f"(acc[mi][nj][3])
                        : "r"(af[mi][0]), "r"(af[mi][1]), "r"(af[mi][2]), "r"(af[mi][3]),
                          "r"(bfr[nj][0]), "r"(bfr[nj][1]));
        }

        if (have_next) {
            const int nb = cur ^ 1;
#pragma unroll
            for (int j = 0; j < 2; ++j) {
                int idx = tid + (j << 8);
                int r = idx >> 2, c = (idx & 3) << 3;
                *(uint4*)&As[nb][r][c] = aR[j];
                *(uint4*)&Bs[nb][r][c] = bRh[j];
            }
        }
        __syncthreads();
    }

    const int g  = lane >> 2;
    const int tg = lane & 3;
#pragma unroll
    for (int mi = 0; mi < 2; ++mi) {
#pragma unroll
        for (int nj = 0; nj < 8; ++nj) {
            int row0 = blockM + wm * 32 + mi * 16 + g;
            int col  = blockN + wn * 64 + nj * 8 + tg * 2;
            if (row0 < M)
                *(float2*)(C + (size_t)row0 * N + col) = make_float2(acc[mi][nj][0], acc[mi][nj][1]);
            int row1 = row0 + 8;
            if (row1 < M)
                *(float2*)(C + (size_t)row1 * N + col) = make_float2(acc[mi][nj][2], acc[mi][nj][3]);
        }
    }
}

// ---------------- GRU gate fusion -------------------------------------------------
__device__ __forceinline__ float sigmoidf_(float x) { return 1.f / (1.f + expf(-x)); }

__global__ void gru_gate_k(
    const float* __restrict__ GL, const float* __restrict__ GR,
    const float* __restrict__ hin,
    const float* __restrict__ bihl, const float* __restrict__ bhhl,
    const float* __restrict__ bihr, const float* __restrict__ bhhr,
    float* __restrict__ hout, __nv_bfloat16* __restrict__ houtb,
    int M, int nparts)
{
    int i = blockIdx.x * blockDim.x + threadIdx.x;
    if (i >= M * HID) return;
    int p = i >> 10;
    int j = i & (HID - 1);
    float h = hin[(size_t)p * HID + j];

    float l0 = 0.f, l1 = 0.f, l2 = 0.f, r0 = 0.f, r1 = 0.f, r2 = 0.f;
    const size_t pstride = (size_t)M * 3 * HID;
    const float* gl = GL + (size_t)p * 3 * HID;
    const float* gr = GR + (size_t)p * 3 * HID;
    for (int q = 0; q < nparts; ++q) {
        l0 += gl[j]; l1 += gl[HID + j]; l2 += gl[2 * HID + j];
        r0 += gr[j]; r1 += gr[HID + j]; r2 += gr[2 * HID + j];
        gl += pstride; gr += pstride;
    }
    {
        float r = sigmoidf_(l0 + bhhl[j] + bihl[j]);
        float z = sigmoidf_(l1 + bhhl[HID + j] + bihl[HID + j]);
        float n = tanhf(bihl[2 * HID + j] + r * (l2 + bhhl[2 * HID + j]));
        float v = (1.f - z) * n + z * h;
        size_t o = (size_t)(2 * p) * HID + j;
        hout[o] = v; houtb[o] = __float2bfloat16(v);
    }
    {
        float r = sigmoidf_(r0 + bhhr[j] + bihr[j]);
        float z = sigmoidf_(r1 + bhhr[HID + j] + bihr[HID + j]);
        float n = tanhf(bihr[2 * HID + j] + r * (r2 + bhhr[2 * HID + j]));
        float v = (1.f - z) * n + z * h;
        size_t o = (size_t)(2 * p + 1) * HID + j;
        hout[o] = v; houtb[o] = __float2bfloat16(v);
    }
}

// ================= final GEMM int8: 4-stage BK=64 pipeline =======================
// 128x128 tile, BK=64 int8, 4-stage cp.async ring, IMMA m16n8k32.
#define IS_STAGE (128 * IKP)                 // 10240 B per operand per stage
#define ISMEM_BYTES (8 * IS_STAGE)           // 4 stages * (A+B) = 81920

__global__ __launch_bounds__(256, 2) void gemm_final_i8_k(
    const int8_t* __restrict__ A,        // [2048,1024] int8
    const int8_t* __restrict__ B,        // [32000,1024] int8
    const float* __restrict__ ascale,    // [2048] per-row h scale
    __nv_bfloat16* __restrict__ C)       // [2048,32000] bf16
{
    extern __shared__ int8_t is[];
    const int tid  = threadIdx.x;
    const int lane = tid & 31;
    const int warp = tid >> 5;
    const int wm   = warp & 3;
    const int wn   = warp >> 2;
    const int blockM = blockIdx.x * 128;    // M fast -> B tile L2 reuse
    const int blockN = blockIdx.y * 128;

    const int8_t* gA = A + (size_t)blockM * HID;
    const int8_t* gB = B + (size_t)blockN * HID;

    int acc[2][8][4];
#pragma unroll
    for (int mi = 0; mi < 2; ++mi)
#pragma unroll
        for (int nj = 0; nj < 8; ++nj)
#pragma unroll
            for (int q = 0; q < 4; ++q) acc[mi][nj][q] = 0;

    // stage s: A at is + (2s)*IS_STAGE, B at +(2s+1)*IS_STAGE; 64 B per row
    auto load_stage = [&](int t) {
        const int s = t & 3;
        int8_t* sa = is + (2 * s) * IS_STAGE;
        int8_t* sb = is + (2 * s + 1) * IS_STAGE;
        const int kof = t * 64;
#pragma unroll
        for (int i = 0; i < 2; ++i) {        // 128 rows x 64 B = 512 chunks of 16B
            int idx = tid + (i << 8);
            int r = idx >> 2, c = (idx & 3) * 16;
            uint32_t dst = (uint32_t)__cvta_generic_to_shared(sa + r * IKP + c);
            const void* src = gA + (size_t)r * HID + kof + c;
            asm volatile("cp.async.cg.shared.global [%0], [%1], 16;" :: "r"(dst), "l"(src));
        }
#pragma unroll
        for (int i = 0; i < 2; ++i) {
            int idx = tid + (i << 8);
            int r = idx >> 2, c = (idx & 3) * 16;
            uint32_t dst = (uint32_t)__cvta_generic_to_shared(sb + r * IKP + c);
            const void* src = gB + (size_t)r * HID + kof + c;
            asm volatile("cp.async.cg.shared.global [%0], [%1], 16;" :: "r"(dst), "l"(src));
        }
        asm volatile("cp.async.commit_group;" ::: "memory");
    };

    // prologue: 3 stages in flight
    load_stage(0);
    load_stage(1);
    load_stage(2);

#pragma unroll 1
    for (int t = 0; t < 16; ++t) {
        // wait for stage t (outstanding after: min(2, 15 - t))
        if (t < 14)      asm volatile("cp.async.wait_group 2;" ::: "memory");
        else if (t < 15) asm volatile("cp.async.wait_group 1;" ::: "memory");
        else             asm volatile("cp.async.wait_group 0;" ::: "memory");
        __syncthreads();

        const int s = t & 3;
        const int8_t* sa = is + (2 * s) * IS_STAGE;
        const int8_t* sb = is + (2 * s + 1) * IS_STAGE;
#pragma unroll
        for (int kk = 0; kk < 2; ++kk) {     // 2 x k32 per BK=64
            uint32_t af[2][4];
#pragma unroll
            for (int mi = 0; mi < 2; ++mi) {
                int row = wm * 32 + mi * 16 + (lane & 15);
                int cb  = kk * 32 + (lane >> 4) * 16;
                uint32_t addr = (uint32_t)__cvta_generic_to_shared(sa + row * IKP + cb);
                asm volatile("ldmatrix.sync.aligned.m8n8.x4.shared.b16 {%0,%1,%2,%3}, [%4];\n"
                             : "=r"(af[mi][0]), "=r"(af[mi][1]), "=r"(af[mi][2]), "=r"(af[mi][3])
                             : "r"(addr));
            }
            uint32_t bfr[8][2];
#pragma unroll
            for (int njp = 0; njp < 4; ++njp) {           // paired x4 B fragments
                int nrow = wn * 64 + njp * 16 + ((lane >> 4) << 3) + (lane & 7);
                int cb   = kk * 32 + ((lane >> 3) & 1) * 16;
                uint32_t addr = (uint32_t)__cvta_generic_to_shared(sb + nrow * IKP + cb);
                asm volatile("ldmatrix.sync.aligned.m8n8.x4.shared.b16 {%0,%1,%2,%3}, [%4];\n"
                             : "=r"(bfr[2 * njp][0]), "=r"(bfr[2 * njp][1]),
                               "=r"(bfr[2 * njp + 1][0]), "=r"(bfr[2 * njp + 1][1])
                             : "r"(addr));
            }
#pragma unroll
            for (int mi = 0; mi < 2; ++mi)
#pragma unroll
                for (int nj = 0; nj < 8; ++nj)
                    asm volatile(
                        "mma.sync.aligned.m16n8k32.row.col.s32.s8.s8.s32 "
                        "{%0,%1,%2,%3}, {%4,%5,%6,%7}, {%8,%9}, {%0,%1,%2,%3};\n"
                        : "+r"(acc[mi][nj][0]), "+r"(acc[mi][nj][1]),
                          "+r"(acc[mi][nj][2]), "+r"(acc[mi][nj][3])
                        : "r"(af[mi][0]), "r"(af[mi][1]), "r"(af[mi][2]), "r"(af[mi][3]),
                          "r"(bfr[nj][0]), "r"(bfr[nj][1]));
        }
        __syncthreads();
        if (t + 3 < 16) load_stage(t + 3);   // refill buffer (t+3)%4 (freed at t-1)
    }

    // ---- epilogue: scale s32 -> f32 -> bf16 ----
    const float SW = 1.f / 4064.f;
    const int g  = lane >> 2;
    const int tg = lane & 3;
#pragma unroll
    for (int mi = 0; mi < 2; ++mi) {
        int row0 = blockM + wm * 32 + mi * 16 + g;
        float s0 = ascale[row0] * SW;
        float s1 = ascale[row0 + 8] * SW;
#pragma unroll
        for (int nj = 0; nj < 8; ++nj) {
            int col = blockN + wn * 64 + nj * 8 + tg * 2;
            *(__nv_bfloat162*)(C + (size_t)row0 * VOCAB + col) =
                __floats2bfloat162_rn((float)acc[mi][nj][0] * s0, (float)acc[mi][nj][1] * s0);
            *(__nv_bfloat162*)(C + (size_t)(row0 + 8) * VOCAB + col) =
                __floats2bfloat162_rn((float)acc[mi][nj][2] * s1, (float)acc[mi][nj][3] * s1);
        }
    }
}

// ---------------- log-softmax: online lse (fast __expf), 2-pass -------------------
__global__ __launch_bounds__(512) void logsoftmax2_k(
    const __nv_bfloat16* __restrict__ logits, const float* __restrict__ bout,
    float* __restrict__ out)
{
    __shared__ float sm_m[16], sm_s[16];
    __shared__ float s_lse;

    const int row = blockIdx.x;          // = b*32 + n
    const int b   = row >> 5;
    const int n   = row & 31;
    const __nv_bfloat16* src = logits + (size_t)row * VOCAB;
    float* dst = out + (size_t)(n * BATCH + b) * VOCAB;
    const int t = threadIdx.x;

    float m = -1e30f, s = 0.f;
    for (int v = t * 8; v < VOCAB; v += 4096) {
        uint4 raw = *(const uint4*)(src + v);
        const __nv_bfloat162* h2 = (const __nv_bfloat162*)&raw;
        float4 b0 = *(const float4*)(bout + v);
        float4 b1 = *(const float4*)(bout + v + 4);
        float2 f0 = __bfloat1622float2(h2[0]);
        float2 f1 = __bfloat1622float2(h2[1]);
        float2 f2 = __bfloat1622float2(h2[2]);
        float2 f3 = __bfloat1622float2(h2[3]);
        float x0 = f0.x + b0.x, x1 = f0.y + b0.y, x2 = f1.x + b0.z, x3 = f1.y + b0.w;
        float x4 = f2.x + b1.x, x5 = f2.y + b1.y, x6 = f3.x + b1.z, x7 = f3.y + b1.w;
        float mx = fmaxf(fmaxf(fmaxf(x0, x1), fmaxf(x2, x3)),
                         fmaxf(fmaxf(x4, x5), fmaxf(x6, x7)));
        if (mx > m) { s *= __expf(m - mx); m = mx; }
        s += __expf(x0 - m) + __expf(x1 - m) + __expf(x2 - m) + __expf(x3 - m)
           + __expf(x4 - m) + __expf(x5 - m) + __expf(x6 - m) + __expf(x7 - m);
    }
#pragma unroll
    for (int o = 16; o; o >>= 1) {
        float m2 = __shfl_xor_sync(0xffffffffu, m, o);
        float s2 = __shfl_xor_sync(0xffffffffu, s, o);
        float mn = fmaxf(m, m2);
        s = s * __expf(m - mn) + s2 * __expf(m2 - mn);
        m = mn;
    }
    if ((t & 31) == 0) { sm_m[t >> 5] = m; sm_s[t >> 5] = s; }
    __syncthreads();
    if (t == 0) {
        float mm = sm_m[0], ss = sm_s[0];
#pragma unroll
        for (int i = 1; i < 16; ++i) {
            float mn = fmaxf(mm, sm_m[i]);
            ss = ss * __expf(mm - mn) + sm_s[i] * __expf(sm_m[i] - mn);
            mm = mn;
        }
        s_lse = mm + logf(ss);
    }
    __syncthreads();
    const float lse = s_lse;

    for (int v = t * 8; v < VOCAB; v += 4096) {
        uint4 raw = *(const uint4*)(src + v);
        const __nv_bfloat162* h2 = (const __nv_bfloat162*)&raw;
        float4 b0 = *(const float4*)(bout + v);
        float4 b1 = *(const float4*)(bout + v + 4);
        float2 f0 = __bfloat1622float2(h2[0]);
        float2 f1 = __bfloat1622float2(h2[1]);
        float2 f2 = __bfloat1622float2(h2[2]);
        float2 f3 = __bfloat1622float2(h2[3]);
        float4 y0 = make_float4(f0.x + b0.x - lse, f0.y + b0.y - lse,
                                f1.x + b0.z - lse, f1.y + b0.w - lse);
        float4 y1 = make_float4(f2.x + b1.x - lse, f2.y + b1.y - lse,
                                f3.x + b1.z - lse, f3.y + b1.w - lse);
        *(float4*)(dst + v)     = y0;
        *(float4*)(dst + v + 4) = y1;
    }
}

// ---------------- host orchestration -------------------------------------------
extern "C" void kernel_launch(void* const* d_in, const int* in_sizes, int n_in,
                              void* d_out, int out_size)
{
    (void)in_sizes; (void)n_in; (void)out_size;
    const float* enc  = (const float*)d_in[0];
    const float* Whhl = (const float*)d_in[1];
    const float* bihl = (const float*)d_in[2];
    const float* bhhl = (const float*)d_in[3];
    const float* Whhr = (const float*)d_in[4];
    const float* bihr = (const float*)d_in[5];
    const float* bhhr = (const float*)d_in[6];
    const float* Wout = (const float*)d_in[7];
    const float* bout = (const float*)d_in[8];

    float *hA, *hB, *gl, *gr, *hscale;
    __nv_bfloat16 *hAb, *hBb, *encb, *wlb, *wrb, *lgb;
    int8_t *wq, *hq;
    cudaGetSymbolAddress((void**)&hA,     g_hA);
    cudaGetSymbolAddress((void**)&hB,     g_hB);
    cudaGetSymbolAddress((void**)&hAb,    g_hAb);
    cudaGetSymbolAddress((void**)&hBb,    g_hBb);
    cudaGetSymbolAddress((void**)&encb,   g_encb);
    cudaGetSymbolAddress((void**)&wlb,    g_wlb);
    cudaGetSymbolAddress((void**)&wrb,    g_wrb);
    cudaGetSymbolAddress((void**)&gl,     g_gl);
    cudaGetSymbolAddress((void**)&gr,     g_gr);
    cudaGetSymbolAddress((void**)&wq,     g_wq);
    cudaGetSymbolAddress((void**)&hq,     g_hq);
    cudaGetSymbolAddress((void**)&hscale, g_hscale);
    cudaGetSymbolAddress((void**)&lgb,    g_logitsb);

    convert_init_k<<<512, 256>>>(Whhl, Whhr, enc, wlb, wrb, encb);
    quant_w_k<<<2048, 256>>>(Wout, wq);

    const float* hin_fp = enc;
    const __nv_bfloat16* hin_bf = encb;
    float* hfp[2] = {hA, hB};
    __nv_bfloat16* hbf[2] = {hAb, hBb};

    int M = BATCH;
    for (int d = 0; d < 5; ++d) {
        int ks = (M <= 128) ? 8 : (M == 256 ? 4 : (M == 512 ? 2 : 1));
        dim3 grid((M + 127) / 128, (3 * HID) / 128, 2 * ks);
        gemm_k<<<grid, 256>>>(hin_bf, wlb, wrb, gl, gr, M, 3 * HID, HID, ks);
        int thr = M * HID;
        gru_gate_k<<<(thr + 255) / 256, 256>>>(gl, gr, hin_fp,
                                               bihl, bhhl, bihr, bhhr,
                                               hfp[d & 1], hbf[d & 1], M, ks);
        hin_fp = hfp[d & 1];
        hin_bf = hbf[d & 1];
        M <<= 1;
    }

    quant_h_k<<<ROWS_FINAL, 256>>>(hin_fp, hq, hscale);

    cudaFuncSetAttribute(gemm_final_i8_k, cudaFuncAttributeMaxDynamicSharedMemorySize,
                         ISMEM_BYTES);
    dim3 grid2(ROWS_FINAL / 128, VOCAB / 128, 1);   // x = M fast (B-tile L2 reuse)
    gemm_final_i8_k<<<grid2, 256, ISMEM_BYTES>>>(hq, wq, hscale, lgb);

    logsoftmax2_k<<<ROWS_FINAL, 512>>>(lgb, bout, (float*)d_out);
}

// round 16
// speedup vs baseline: 1.0536x; 1.0536x over previous
#include <cuda_runtime.h>
#include <cuda_bf16.h>
#include <math.h>
#include <stdint.h>

#define HID   1024
#define VOCAB 32000
#define BATCH 64
#define ROWS_FINAL (BATCH * 32)      // 2048
#define BKP 40                        // tree GEMM smem row stride (32 + 8 pad)
#define IKP 144                       // int8 GEMM smem row stride BYTES (128 + 16 pad)

// ---------------- static device scratch (no allocations allowed) ----------------
__device__ float g_hA[ROWS_FINAL * HID];                 // fp32 h ping
__device__ float g_hB[ROWS_FINAL * HID];                 // fp32 h pong
__device__ __nv_bfloat16 g_hAb[ROWS_FINAL * HID];        // bf16 h ping
__device__ __nv_bfloat16 g_hBb[ROWS_FINAL * HID];        // bf16 h pong
__device__ __nv_bfloat16 g_encb[BATCH * HID];            // bf16 encoding
__device__ __nv_bfloat16 g_wlb[3 * HID * HID];           // bf16 Whh_l
__device__ __nv_bfloat16 g_wrb[3 * HID * HID];           // bf16 Whh_r
__device__ float g_gl[1024 * 3 * HID];                   // split-K partials
__device__ float g_gr[1024 * 3 * HID];
__device__ int8_t g_wq[(size_t)VOCAB * HID];             // int8 Wout (scale 1/4064)
__device__ int8_t g_hq[ROWS_FINAL * HID];                // int8 h (per-row scale)
__device__ float  g_hscale[ROWS_FINAL];
__device__ __nv_bfloat16 g_logitsb[(size_t)ROWS_FINAL * VOCAB]; // bf16 logits (bias folded)

// ---------------- one-time conversions -------------------------------------------
__global__ void convert_init_k(const float* __restrict__ wl, const float* __restrict__ wr,
                               const float* __restrict__ enc,
                               __nv_bfloat16* __restrict__ wlb, __nv_bfloat16* __restrict__ wrb,
                               __nv_bfloat16* __restrict__ encb)
{
    const long nW = 3L * HID * HID / 2;
    const long ne = BATCH * HID / 2;
    const long tot = 2 * nW + ne;
    for (long i = (long)blockIdx.x * blockDim.x + threadIdx.x; i < tot;
         i += (long)gridDim.x * blockDim.x) {
        const float2* src; __nv_bfloat162* dst; long off;
        if (i < nW)          { src = (const float2*)wl;  dst = (__nv_bfloat162*)wlb;  off = i; }
        else if (i < 2 * nW) { src = (const float2*)wr;  dst = (__nv_bfloat162*)wrb;  off = i - nW; }
        else                 { src = (const float2*)enc; dst = (__nv_bfloat162*)encb; off = i - 2 * nW; }
        float2 v = src[off];
        dst[off] = __floats2bfloat162_rn(v.x, v.y);
    }
}

__global__ void quant_w_k(const float* __restrict__ wo, int8_t* __restrict__ wq)
{
    const long n4 = (long)VOCAB * HID / 4;
    for (long i = (long)blockIdx.x * blockDim.x + threadIdx.x; i < n4;
         i += (long)gridDim.x * blockDim.x) {
        float4 v = ((const float4*)wo)[i];
        char4 q;
        q.x = (char)max(-127.f, min(127.f, rintf(v.x * 4064.f)));
        q.y = (char)max(-127.f, min(127.f, rintf(v.y * 4064.f)));
        q.z = (char)max(-127.f, min(127.f, rintf(v.z * 4064.f)));
        q.w = (char)max(-127.f, min(127.f, rintf(v.w * 4064.f)));
        ((char4*)wq)[i] = q;
    }
}

__global__ __launch_bounds__(256) void quant_h_k(const float* __restrict__ h,
                                                 int8_t* __restrict__ hq,
                                                 float* __restrict__ hscale)
{
    __shared__ float smax[8];
    const int row = blockIdx.x;
    const int t = threadIdx.x;
    const float4 v = ((const float4*)(h + (size_t)row * HID))[t];
    float m = fmaxf(fmaxf(fabsf(v.x), fabsf(v.y)), fmaxf(fabsf(v.z), fabsf(v.w)));
#pragma unroll
    for (int o = 16; o; o >>= 1) m = fmaxf(m, __shfl_xor_sync(0xffffffffu, m, o));
    if ((t & 31) == 0) smax[t >> 5] = m;
    __syncthreads();
    float rm = fmaxf(fmaxf(fmaxf(smax[0], smax[1]), fmaxf(smax[2], smax[3])),
                     fmaxf(fmaxf(smax[4], smax[5]), fmaxf(smax[6], smax[7])));
    rm = fmaxf(rm, 1e-8f);
    const float inv = 127.f / rm;
    char4 q;
    q.x = (char)rintf(v.x * inv);
    q.y = (char)rintf(v.y * inv);
    q.z = (char)rintf(v.z * inv);
    q.w = (char)rintf(v.w * inv);
    ((char4*)(hq + (size_t)row * HID))[t] = q;
    if (t == 0) hscale[row] = rm / 127.f;
}

// ---------------- tree-level GEMM (mma.sync; split-K fused L/R) ------------------
__global__ __launch_bounds__(256) void gemm_k(
    const __nv_bfloat16* __restrict__ A,
    const void* __restrict__ Bl, const void* __restrict__ Br,
    float* __restrict__ Cl, float* __restrict__ Cr,
    int M, int N, int K, int ksplit)
{
    __shared__ __nv_bfloat16 As[2][128][BKP];
    __shared__ __nv_bfloat16 Bs[2][128][BKP];

    const int tid  = threadIdx.x;
    const int lane = tid & 31;
    const int warp = tid >> 5;
    const int wm   = warp & 3;
    const int wn   = warp >> 2;
    const int blockM = blockIdx.x * 128;
    const int blockN = blockIdx.y * 128;

    int w = blockIdx.z & 1, part = blockIdx.z >> 1;
    const void* Bv = w ? Br : Bl;
    float* C = (w ? Cr : Cl) + (size_t)part * M * N;
    const int Kc  = K / ksplit;
    const int k0b = part * Kc;

    float acc[2][8][4];
#pragma unroll
    for (int mi = 0; mi < 2; ++mi)
#pragma unroll
        for (int nj = 0; nj < 8; ++nj)
#pragma unroll
            for (int q = 0; q < 4; ++q) acc[mi][nj][q] = 0.f;

    uint4 aR[2], bRh[2];

    {
        const int k0 = k0b;
#pragma unroll
        for (int j = 0; j < 2; ++j) {
            int idx = tid + (j << 8);
            int r = idx >> 2, c = (idx & 3) << 3;
            int grow = blockM + r;
            aR[j] = (grow < M) ? *(const uint4*)(A + (size_t)grow * K + k0 + c)
                               : make_uint4(0, 0, 0, 0);
            bRh[j] = *(const uint4*)((const __nv_bfloat16*)Bv + (size_t)(blockN + r) * K + k0 + c);
        }
#pragma unroll
        for (int j = 0; j < 2; ++j) {
            int idx = tid + (j << 8);
            int r = idx >> 2, c = (idx & 3) << 3;
            *(uint4*)&As[0][r][c] = aR[j];
            *(uint4*)&Bs[0][r][c] = bRh[j];
        }
    }
    __syncthreads();

    const int kTiles = Kc >> 5;
    for (int kt = 0; kt < kTiles; ++kt) {
        const int cur = kt & 1;
        const bool have_next = (kt + 1 < kTiles);
        if (have_next) {
            const int k0 = k0b + ((kt + 1) << 5);
#pragma unroll
            for (int j = 0; j < 2; ++j) {
                int idx = tid + (j << 8);
                int r = idx >> 2, c = (idx & 3) << 3;
                int grow = blockM + r;
                aR[j] = (grow < M) ? *(const uint4*)(A + (size_t)grow * K + k0 + c)
                                   : make_uint4(0, 0, 0, 0);
                bRh[j] = *(const uint4*)((const __nv_bfloat16*)Bv + (size_t)(blockN + r) * K + k0 + c);
            }
        }

#pragma unroll
        for (int kk = 0; kk < 2; ++kk) {
            uint32_t af[2][4];
#pragma unroll
            for (int mi = 0; mi < 2; ++mi) {
                int row = wm * 32 + mi * 16 + (lane & 15);
                int col = kk * 16 + (lane >> 4) * 8;
                uint32_t addr = (uint32_t)__cvta_generic_to_shared(&As[cur][row][col]);
                asm volatile("ldmatrix.sync.aligned.m8n8.x4.shared.b16 {%0,%1,%2,%3}, [%4];\n"
                             : "=r"(af[mi][0]), "=r"(af[mi][1]), "=r"(af[mi][2]), "=r"(af[mi][3])
                             : "r"(addr));
            }
            uint32_t bfr[8][2];
#pragma unroll
            for (int njp = 0; njp < 4; ++njp) {
                int nrow = wn * 64 + njp * 16 + ((lane >> 4) << 3) + (lane & 7);
                int col  = kk * 16 + ((lane >> 3) & 1) * 8;
                uint32_t addr = (uint32_t)__cvta_generic_to_shared(&Bs[cur][nrow][col]);
                asm volatile("ldmatrix.sync.aligned.m8n8.x4.shared.b16 {%0,%1,%2,%3}, [%4];\n"
                             : "=r"(bfr[2 * njp][0]), "=r"(bfr[2 * njp][1]),
                               "=r"(bfr[2 * njp + 1][0]), "=r"(bfr[2 * njp + 1][1])
                             : "r"(addr));
            }
#pragma unroll
            for (int mi = 0; mi < 2; ++mi)
#pragma unroll
                for (int nj = 0; nj < 8; ++nj)
                    asm volatile(
                        "mma.sync.aligned.m16n8k16.row.col.f32.bf16.bf16.f32 "
                        "{%0,%1,%2,%3}, {%4,%5,%6,%7}, {%8,%9}, {%0,%1,%2,%3};\n"
                        : "+f"(acc[mi][nj][0]), "+f"(acc[mi][nj][1]),
                          "+f"(acc[mi][nj][2]), "+f"(acc[mi][nj][3])
                        : "r"(af[mi][0]), "r"(af[mi][1]), "r"(af[mi][2]), "r"(af[mi][3]),
                          "r"(bfr[nj][0]), "r"(bfr[nj][1]));
        }

        if (have_next) {
            const int nb = cur ^ 1;
#pragma unroll
            for (int j = 0; j < 2; ++j) {
                int idx = tid + (j << 8);
                int r = idx >> 2, c = (idx & 3) << 3;
                *(uint4*)&As[nb][r][c] = aR[j];
                *(uint4*)&Bs[nb][r][c] = bRh[j];
            }
        }
        __syncthreads();
    }

    const int g  = lane >> 2;
    const int tg = lane & 3;
#pragma unroll
    for (int mi = 0; mi < 2; ++mi) {
#pragma unroll
        for (int nj = 0; nj < 8; ++nj) {
            int row0 = blockM + wm * 32 + mi * 16 + g;
            int col  = blockN + wn * 64 + nj * 8 + tg * 2;
            if (row0 < M)
                *(float2*)(C + (size_t)row0 * N + col) = make_float2(acc[mi][nj][0], acc[mi][nj][1]);
            int row1 = row0 + 8;
            if (row1 < M)
                *(float2*)(C + (size_t)row1 * N + col) = make_float2(acc[mi][nj][2], acc[mi][nj][3]);
        }
    }
}

// ---------------- GRU gate fusion -------------------------------------------------
__device__ __forceinline__ float sigmoidf_(float x) { return 1.f / (1.f + expf(-x)); }

__global__ void gru_gate_k(
    const float* __restrict__ GL, const float* __restrict__ GR,
    const float* __restrict__ hin,
    const float* __restrict__ bihl, const float* __restrict__ bhhl,
    const float* __restrict__ bihr, const float* __restrict__ bhhr,
    float* __restrict__ hout, __nv_bfloat16* __restrict__ houtb,
    int M, int nparts)
{
    int i = blockIdx.x * blockDim.x + threadIdx.x;
    if (i >= M * HID) return;
    int p = i >> 10;
    int j = i & (HID - 1);
    float h = hin[(size_t)p * HID + j];

    float l0 = 0.f, l1 = 0.f, l2 = 0.f, r0 = 0.f, r1 = 0.f, r2 = 0.f;
    const size_t pstride = (size_t)M * 3 * HID;
    const float* gl = GL + (size_t)p * 3 * HID;
    const float* gr = GR + (size_t)p * 3 * HID;
    for (int q = 0; q < nparts; ++q) {
        l0 += gl[j]; l1 += gl[HID + j]; l2 += gl[2 * HID + j];
        r0 += gr[j]; r1 += gr[HID + j]; r2 += gr[2 * HID + j];
        gl += pstride; gr += pstride;
    }
    {
        float r = sigmoidf_(l0 + bhhl[j] + bihl[j]);
        float z = sigmoidf_(l1 + bhhl[HID + j] + bihl[HID + j]);
        float n = tanhf(bihl[2 * HID + j] + r * (l2 + bhhl[2 * HID + j]));
        float v = (1.f - z) * n + z * h;
        size_t o = (size_t)(2 * p) * HID + j;
        hout[o] = v; houtb[o] = __float2bfloat16(v);
    }
    {
        float r = sigmoidf_(r0 + bhhr[j] + bihr[j]);
        float z = sigmoidf_(r1 + bhhr[HID + j] + bihr[HID + j]);
        float n = tanhf(bihr[2 * HID + j] + r * (r2 + bhhr[2 * HID + j]));
        float v = (1.f - z) * n + z * h;
        size_t o = (size_t)(2 * p + 1) * HID + j;
        hout[o] = v; houtb[o] = __float2bfloat16(v);
    }
}

// ================= final GEMM int8 (R12 shape) + bias folded into epilogue =======
#define IS_STAGE (128 * IKP)
#define ISMEM_BYTES (4 * IS_STAGE)

__global__ __launch_bounds__(256, 2) void gemm_final_i8_k(
    const int8_t* __restrict__ A,        // [2048,1024] int8
    const int8_t* __restrict__ B,        // [32000,1024] int8
    const float* __restrict__ ascale,    // [2048] per-row h scale
    const float* __restrict__ bout,      // [32000] bias
    __nv_bfloat16* __restrict__ C)       // [2048,32000] bf16 (logit + bias)
{
    extern __shared__ int8_t is[];
    const int tid  = threadIdx.x;
    const int lane = tid & 31;
    const int warp = tid >> 5;
    const int wm   = warp & 3;
    const int wn   = warp >> 2;
    const int blockM = blockIdx.x * 128;    // M fast -> B tile L2 reuse
    const int blockN = blockIdx.y * 128;

    const int8_t* gA = A + (size_t)blockM * HID;
    const int8_t* gB = B + (size_t)blockN * HID;

    int acc[2][8][4];
#pragma unroll
    for (int mi = 0; mi < 2; ++mi)
#pragma unroll
        for (int nj = 0; nj < 8; ++nj)
#pragma unroll
            for (int q = 0; q < 4; ++q) acc[mi][nj][q] = 0;

    auto load_stage = [&](int t, int s) {
        int8_t* sa = is + (2 * s) * IS_STAGE;
        int8_t* sb = is + (2 * s + 1) * IS_STAGE;
        const int kof = t * 128;
#pragma unroll
        for (int i = 0; i < 4; ++i) {
            int idx = tid + (i << 8);
            int r = idx >> 3, c = (idx & 7) * 16;
            uint32_t dst = (uint32_t)__cvta_generic_to_shared(sa + r * IKP + c);
            const void* src = gA + (size_t)r * HID + kof + c;
            asm volatile("cp.async.cg.shared.global [%0], [%1], 16;" :: "r"(dst), "l"(src));
        }
#pragma unroll
        for (int i = 0; i < 4; ++i) {
            int idx = tid + (i << 8);
            int r = idx >> 3, c = (idx & 7) * 16;
            uint32_t dst = (uint32_t)__cvta_generic_to_shared(sb + r * IKP + c);
            const void* src = gB + (size_t)r * HID + kof + c;
            asm volatile("cp.async.cg.shared.global [%0], [%1], 16;" :: "r"(dst), "l"(src));
        }
        asm volatile("cp.async.commit_group;" ::: "memory");
    };

    load_stage(0, 0);

#pragma unroll 1
    for (int t = 0; t < 8; ++t) {
        const int cur = t & 1;
        if (t + 1 < 8) {
            load_stage(t + 1, cur ^ 1);
            asm volatile("cp.async.wait_group 1;" ::: "memory");
        } else {
            asm volatile("cp.async.wait_group 0;" ::: "memory");
        }
        __syncthreads();

        const int8_t* sa = is + (2 * cur) * IS_STAGE;
        const int8_t* sb = is + (2 * cur + 1) * IS_STAGE;
#pragma unroll
        for (int kk = 0; kk < 4; ++kk) {
            uint32_t af[2][4];
#pragma unroll
            for (int mi = 0; mi < 2; ++mi) {
                int row = wm * 32 + mi * 16 + (lane & 15);
                int cb  = kk * 32 + (lane >> 4) * 16;
                uint32_t addr = (uint32_t)__cvta_generic_to_shared(sa + row * IKP + cb);
                asm volatile("ldmatrix.sync.aligned.m8n8.x4.shared.b16 {%0,%1,%2,%3}, [%4];\n"
                             : "=r"(af[mi][0]), "=r"(af[mi][1]), "=r"(af[mi][2]), "=r"(af[mi][3])
                             : "r"(addr));
            }
            uint32_t bfr[8][2];
#pragma unroll
            for (int njp = 0; njp < 4; ++njp) {
                int nrow = wn * 64 + njp * 16 + ((lane >> 4) << 3) + (lane & 7);
                int cb   = kk * 32 + ((lane >> 3) & 1) * 16;
                uint32_t addr = (uint32_t)__cvta_generic_to_shared(sb + nrow * IKP + cb);
                asm volatile("ldmatrix.sync.aligned.m8n8.x4.shared.b16 {%0,%1,%2,%3}, [%4];\n"
                             : "=r"(bfr[2 * njp][0]), "=r"(bfr[2 * njp][1]),
                               "=r"(bfr[2 * njp + 1][0]), "=r"(bfr[2 * njp + 1][1])
                             : "r"(addr));
            }
#pragma unroll
            for (int mi = 0; mi < 2; ++mi)
#pragma unroll
                for (int nj = 0; nj < 8; ++nj)
                    asm volatile(
                        "mma.sync.aligned.m16n8k32.row.col.s32.s8.s8.s32 "
                        "{%0,%1,%2,%3}, {%4,%5,%6,%7}, {%8,%9}, {%0,%1,%2,%3};\n"
                        : "+r"(acc[mi][nj][0]), "+r"(acc[mi][nj][1]),
                          "+r"(acc[mi][nj][2]), "+r"(acc[mi][nj][3])
                        : "r"(af[mi][0]), "r"(af[mi][1]), "r"(af[mi][2]), "r"(af[mi][3]),
                          "r"(bfr[nj][0]), "r"(bfr[nj][1]));
        }
        __syncthreads();
    }

    // ---- epilogue: scale s32 -> f32, add bias, store bf16 ----
    const float SW = 1.f / 4064.f;
    const int g  = lane >> 2;
    const int tg = lane & 3;

    float2 bb[8];
#pragma unroll
    for (int nj = 0; nj < 8; ++nj)
        bb[nj] = *(const float2*)(bout + blockN + wn * 64 + nj * 8 + tg * 2);

#pragma unroll
    for (int mi = 0; mi < 2; ++mi) {
        int row0 = blockM + wm * 32 + mi * 16 + g;
        float s0 = ascale[row0] * SW;
        float s1 = ascale[row0 + 8] * SW;
#pragma unroll
        for (int nj = 0; nj < 8; ++nj) {
            int col = blockN + wn * 64 + nj * 8 + tg * 2;
            *(__nv_bfloat162*)(C + (size_t)row0 * VOCAB + col) =
                __floats2bfloat162_rn((float)acc[mi][nj][0] * s0 + bb[nj].x,
                                      (float)acc[mi][nj][1] * s0 + bb[nj].y);
            *(__nv_bfloat162*)(C + (size_t)(row0 + 8) * VOCAB + col) =
                __floats2bfloat162_rn((float)acc[mi][nj][2] * s1 + bb[nj].x,
                                      (float)acc[mi][nj][3] * s1 + bb[nj].y);
        }
    }
}

// ---------------- log-softmax: bias pre-folded, online lse, 2-pass ----------------
__global__ __launch_bounds__(512) void logsoftmax2_k(
    const __nv_bfloat16* __restrict__ logits, float* __restrict__ out)
{
    __shared__ float sm_m[16], sm_s[16];
    __shared__ float s_lse;

    const int row = blockIdx.x;          // = b*32 + n
    const int b   = row >> 5;
    const int n   = row & 31;
    const __nv_bfloat16* src = logits + (size_t)row * VOCAB;
    float* dst = out + (size_t)(n * BATCH + b) * VOCAB;
    const int t = threadIdx.x;

    float m = -1e30f, s = 0.f;
    for (int v = t * 8; v < VOCAB; v += 4096) {
        uint4 raw = *(const uint4*)(src + v);
        const __nv_bfloat162* h2 = (const __nv_bfloat162*)&raw;
        float2 f0 = __bfloat1622float2(h2[0]);
        float2 f1 = __bfloat1622float2(h2[1]);
        float2 f2 = __bfloat1622float2(h2[2]);
        float2 f3 = __bfloat1622float2(h2[3]);
        float mx = fmaxf(fmaxf(fmaxf(f0.x, f0.y), fmaxf(f1.x, f1.y)),
                         fmaxf(fmaxf(f2.x, f2.y), fmaxf(f3.x, f3.y)));
        if (mx > m) { s *= __expf(m - mx); m = mx; }
        s += __expf(f0.x - m) + __expf(f0.y - m) + __expf(f1.x - m) + __expf(f1.y - m)
           + __expf(f2.x - m) + __expf(f2.y - m) + __expf(f3.x - m) + __expf(f3.y - m);
    }
#pragma unroll
    for (int o = 16; o; o >>= 1) {
        float m2 = __shfl_xor_sync(0xffffffffu, m, o);
        float s2 = __shfl_xor_sync(0xffffffffu, s, o);
        float mn = fmaxf(m, m2);
        s = s * __expf(m - mn) + s2 * __expf(m2 - mn);
        m = mn;
    }
    if ((t & 31) == 0) { sm_m[t >> 5] = m; sm_s[t >> 5] = s; }
    __syncthreads();
    if (t == 0) {
        float mm = sm_m[0], ss = sm_s[0];
#pragma unroll
        for (int i = 1; i < 16; ++i) {
            float mn = fmaxf(mm, sm_m[i]);
            ss = ss * __expf(mm - mn) + sm_s[i] * __expf(sm_m[i] - mn);
            mm = mn;
        }
        s_lse = mm + logf(ss);
    }
    __syncthreads();
    const float lse = s_lse;

    for (int v = t * 8; v < VOCAB; v += 4096) {
        uint4 raw = *(const uint4*)(src + v);
        const __nv_bfloat162* h2 = (const __nv_bfloat162*)&raw;
        float2 f0 = __bfloat1622float2(h2[0]);
        float2 f1 = __bfloat1622float2(h2[1]);
        float2 f2 = __bfloat1622float2(h2[2]);
        float2 f3 = __bfloat1622float2(h2[3]);
        float4 y0 = make_float4(f0.x - lse, f0.y - lse, f1.x - lse, f1.y - lse);
        float4 y1 = make_float4(f2.x - lse, f2.y - lse, f3.x - lse, f3.y - lse);
        *(float4*)(dst + v)     = y0;
        *(float4*)(dst + v + 4) = y1;
    }
}

// ---------------- host orchestration -------------------------------------------
extern "C" void kernel_launch(void* const* d_in, const int* in_sizes, int n_in,
                              void* d_out, int out_size)
{
    (void)in_sizes; (void)n_in; (void)out_size;
    const float* enc  = (const float*)d_in[0];
    const float* Whhl = (const float*)d_in[1];
    const float* bihl = (const float*)d_in[2];
    const float* bhhl = (const float*)d_in[3];
    const float* Whhr = (const float*)d_in[4];
    const float* bihr = (const float*)d_in[5];
    const float* bhhr = (const float*)d_in[6];
    const float* Wout = (const float*)d_in[7];
    const float* bout = (const float*)d_in[8];

    float *hA, *hB, *gl, *gr, *hscale;
    __nv_bfloat16 *hAb, *hBb, *encb, *wlb, *wrb, *lgb;
    int8_t *wq, *hq;
    cudaGetSymbolAddress((void**)&hA,     g_hA);
    cudaGetSymbolAddress((void**)&hB,     g_hB);
    cudaGetSymbolAddress((void**)&hAb,    g_hAb);
    cudaGetSymbolAddress((void**)&hBb,    g_hBb);
    cudaGetSymbolAddress((void**)&encb,   g_encb);
    cudaGetSymbolAddress((void**)&wlb,    g_wlb);
    cudaGetSymbolAddress((void**)&wrb,    g_wrb);
    cudaGetSymbolAddress((void**)&gl,     g_gl);
    cudaGetSymbolAddress((void**)&gr,     g_gr);
    cudaGetSymbolAddress((void**)&wq,     g_wq);
    cudaGetSymbolAddress((void**)&hq,     g_hq);
    cudaGetSymbolAddress((void**)&hscale, g_hscale);
    cudaGetSymbolAddress((void**)&lgb,    g_logitsb);

    convert_init_k<<<512, 256>>>(Whhl, Whhr, enc, wlb, wrb, encb);
    quant_w_k<<<2048, 256>>>(Wout, wq);

    const float* hin_fp = enc;
    const __nv_bfloat16* hin_bf = encb;
    float* hfp[2] = {hA, hB};
    __nv_bfloat16* hbf[2] = {hAb, hBb};

    int M = BATCH;
    for (int d = 0; d < 5; ++d) {
        int ks = (M <= 128) ? 8 : (M == 256 ? 4 : (M == 512 ? 2 : 1));
        dim3 grid((M + 127) / 128, (3 * HID) / 128, 2 * ks);
        gemm_k<<<grid, 256>>>(hin_bf, wlb, wrb, gl, gr, M, 3 * HID, HID, ks);
        int thr = M * HID;
        gru_gate_k<<<(thr + 255) / 256, 256>>>(gl, gr, hin_fp,
                                               bihl, bhhl, bihr, bhhr,
                                               hfp[d & 1], hbf[d & 1], M, ks);
        hin_fp = hfp[d & 1];
        hin_bf = hbf[d & 1];
        M <<= 1;
    }

    quant_h_k<<<ROWS_FINAL, 256>>>(hin_fp, hq, hscale);

    cudaFuncSetAttribute(gemm_final_i8_k, cudaFuncAttributeMaxDynamicSharedMemorySize,
                         ISMEM_BYTES);
    dim3 grid2(ROWS_FINAL / 128, VOCAB / 128, 1);   // x = M fast (B-tile L2 reuse)
    gemm_final_i8_k<<<grid2, 256, ISMEM_BYTES>>>(hq, wq, hscale, bout, lgb);

    logsoftmax2_k<<<ROWS_FINAL, 512>>>(lgb, (float*)d_out);
}